// round 1
// baseline (speedup 1.0000x reference)
#include <cuda_runtime.h>

// Problem constants (B=4, S=2048, EMB=1024, HEADS=16, HEAD_DIM=64)
#define TOK   8192      // B*S
#define EMB_  1024
#define NHEAD 16
#define HDIM  64

// Scratch (static device globals: no allocation allowed)
__device__ float g_v[TOK * EMB_];
__device__ float g_k[TOK * EMB_];
__device__ float g_q[TOK * EMB_];
__device__ float g_att[TOK * EMB_];

// ---------------------------------------------------------------------------
// TN SGEMM: C[M,N] = X[M,K] @ W[N,K]^T + bias[N]
// Both X and W are row-major with K contiguous -> coalesced loads for both.
// Tiles: BM=128, BN=128, BK=16; 256 threads; 8x8 per-thread micro-tile.
// Assumes M%128==0, N%128==0, K%16==0 (holds: 8192/1024/1024).
// ---------------------------------------------------------------------------
__global__ __launch_bounds__(256, 2)
void sgemm_tn(const float* __restrict__ X, const float* __restrict__ W,
              const float* __restrict__ bias, float* __restrict__ C,
              int M, int N, int K)
{
    constexpr int BM = 128, BN = 128, BK = 16, TM = 8, TN = 8;
    __shared__ float As[BK][BM];
    __shared__ float Bs[BK][BN];

    const int tid = threadIdx.x;
    const int tx = tid & 15;        // 0..15 -> N direction
    const int ty = tid >> 4;        // 0..15 -> M direction
    const int rowBase = blockIdx.y * BM;
    const int colBase = blockIdx.x * BN;

    float acc[TM][TN];
#pragma unroll
    for (int i = 0; i < TM; i++)
#pragma unroll
        for (int j = 0; j < TN; j++) acc[i][j] = 0.0f;

    for (int k0 = 0; k0 < K; k0 += BK) {
        // Load 128x16 tiles of X and W (512 float4 each; 2 per thread each).
#pragma unroll
        for (int l = 0; l < 2; l++) {
            const int f = tid + l * 256;     // 0..511
            const int r = f >> 2;            // 0..127
            const int c = (f & 3) << 2;      // 0,4,8,12
            float4 a4 = *(const float4*)(X + (size_t)(rowBase + r) * K + k0 + c);
            As[c + 0][r] = a4.x; As[c + 1][r] = a4.y;
            As[c + 2][r] = a4.z; As[c + 3][r] = a4.w;
            float4 b4 = *(const float4*)(W + (size_t)(colBase + r) * K + k0 + c);
            Bs[c + 0][r] = b4.x; Bs[c + 1][r] = b4.y;
            Bs[c + 2][r] = b4.z; Bs[c + 3][r] = b4.w;
        }
        __syncthreads();

#pragma unroll
        for (int kk = 0; kk < BK; kk++) {
            float a[TM], b[TN];
            *(float4*)&a[0] = *(const float4*)&As[kk][ty * TM + 0];
            *(float4*)&a[4] = *(const float4*)&As[kk][ty * TM + 4];
            *(float4*)&b[0] = *(const float4*)&Bs[kk][tx * TN + 0];
            *(float4*)&b[4] = *(const float4*)&Bs[kk][tx * TN + 4];
#pragma unroll
            for (int i = 0; i < TM; i++)
#pragma unroll
                for (int j = 0; j < TN; j++)
                    acc[i][j] = fmaf(a[i], b[j], acc[i][j]);
        }
        __syncthreads();
    }

    // Epilogue: add bias, store float4.
    float bv[TN];
    *(float4*)&bv[0] = *(const float4*)(bias + colBase + tx * TN + 0);
    *(float4*)&bv[4] = *(const float4*)(bias + colBase + tx * TN + 4);
#pragma unroll
    for (int i = 0; i < TM; i++) {
        const int row = rowBase + ty * TM + i;
        float* cp = C + (size_t)row * N + colBase + tx * TN;
        float4 o0, o1;
        o0.x = acc[i][0] + bv[0]; o0.y = acc[i][1] + bv[1];
        o0.z = acc[i][2] + bv[2]; o0.w = acc[i][3] + bv[3];
        o1.x = acc[i][4] + bv[4]; o1.y = acc[i][5] + bv[5];
        o1.z = acc[i][6] + bv[6]; o1.w = acc[i][7] + bv[7];
        *(float4*)(cp + 0) = o0;
        *(float4*)(cp + 4) = o1;
    }
}

// ---------------------------------------------------------------------------
// Per-token head-axis attention.
// One CTA (256 threads) per token t:
//   scores[h][g] = (1/8) * dot(q[h], k[g])   (h,g in 0..15, dot over 64 dims)
//   attn = softmax_g(scores)
//   out[h][d] = sum_g attn[h][g] * v[g][d]
// ---------------------------------------------------------------------------
__global__ __launch_bounds__(256)
void attn_head_mix(const float* __restrict__ q, const float* __restrict__ k,
                   const float* __restrict__ v, float* __restrict__ out)
{
    __shared__ float sq[NHEAD][HDIM + 1];   // +1 pad: kill stride-64 conflicts
    __shared__ float sk[NHEAD][HDIM + 1];
    __shared__ float sv[NHEAD][HDIM + 1];
    __shared__ float sa[NHEAD * NHEAD];

    const int t = blockIdx.x;
    const int tid = threadIdx.x;
    const size_t base = (size_t)t * EMB_;

    // Stage q,k,v for this token into padded shared memory (coalesced reads).
#pragma unroll
    for (int e = tid; e < EMB_; e += 256) {
        const int h = e >> 6, d = e & 63;
        sq[h][d] = q[base + e];
        sk[h][d] = k[base + e];
        sv[h][d] = v[base + e];
    }
    __syncthreads();

    // One thread per (h,g) score.
    const int h = tid >> 4;
    const int g = tid & 15;
    float s = 0.0f;
#pragma unroll
    for (int d = 0; d < HDIM; d++) s = fmaf(sq[h][d], sk[g][d], s);
    s *= 0.125f;   // HEAD_DIM^-0.5 = 1/8

    // Softmax over g: reduce within 16-lane groups.
    float m = s;
#pragma unroll
    for (int o = 8; o > 0; o >>= 1)
        m = fmaxf(m, __shfl_xor_sync(0xffffffffu, m, o, 16));
    const float e = __expf(s - m);
    float sum = e;
#pragma unroll
    for (int o = 8; o > 0; o >>= 1)
        sum += __shfl_xor_sync(0xffffffffu, sum, o, 16);
    sa[h * 16 + g] = e / sum;
    __syncthreads();

    // Output: thread computes out[ho][d0..d0+3] -> coalesced float4 store.
    const int ho = tid >> 4;
    const int d0 = (tid & 15) * 4;
    float4 o4 = make_float4(0.f, 0.f, 0.f, 0.f);
#pragma unroll
    for (int gg = 0; gg < NHEAD; gg++) {
        const float a = sa[ho * 16 + gg];
        o4.x = fmaf(a, sv[gg][d0 + 0], o4.x);
        o4.y = fmaf(a, sv[gg][d0 + 1], o4.y);
        o4.z = fmaf(a, sv[gg][d0 + 2], o4.z);
        o4.w = fmaf(a, sv[gg][d0 + 3], o4.w);
    }
    *(float4*)(out + base + ho * HDIM + d0) = o4;
}

// ---------------------------------------------------------------------------
// Launch: 3 projection GEMMs -> attention -> output GEMM.
// Inputs (metadata order): values, keys, query, Wv, bv, Wk, bk, Wq, bq, Wo, bo
// ---------------------------------------------------------------------------
extern "C" void kernel_launch(void* const* d_in, const int* in_sizes, int n_in,
                              void* d_out, int out_size)
{
    const float* values = (const float*)d_in[0];
    const float* keys   = (const float*)d_in[1];
    const float* query  = (const float*)d_in[2];
    const float* Wv = (const float*)d_in[3];
    const float* bv = (const float*)d_in[4];
    const float* Wk = (const float*)d_in[5];
    const float* bk = (const float*)d_in[6];
    const float* Wq = (const float*)d_in[7];
    const float* bq = (const float*)d_in[8];
    const float* Wo = (const float*)d_in[9];
    const float* bo = (const float*)d_in[10];
    float* out = (float*)d_out;

    float *gv, *gk, *gq, *ga;
    cudaGetSymbolAddress((void**)&gv, g_v);
    cudaGetSymbolAddress((void**)&gk, g_k);
    cudaGetSymbolAddress((void**)&gq, g_q);
    cudaGetSymbolAddress((void**)&ga, g_att);

    dim3 block(256);
    dim3 grid(EMB_ / 128, TOK / 128);   // (8, 64)

    sgemm_tn<<<grid, block>>>(values, Wv, bv, gv, TOK, EMB_, EMB_);
    sgemm_tn<<<grid, block>>>(keys,   Wk, bk, gk, TOK, EMB_, EMB_);
    sgemm_tn<<<grid, block>>>(query,  Wq, bq, gq, TOK, EMB_, EMB_);

    attn_head_mix<<<TOK, 256>>>(gq, gk, gv, ga);

    sgemm_tn<<<grid, block>>>(ga, Wo, bo, out, TOK, EMB_, EMB_);
}

// round 3
// speedup vs baseline: 2.3920x; 2.3920x over previous
#include <cuda_runtime.h>
#include <cuda_bf16.h>
#include <cstdint>

// Problem constants (B=4, S=2048, EMB=1024, HEADS=16, HEAD_DIM=64)
#define TOK   8192
#define EMB_  1024
#define NHEAD 16
#define HDIM  64

// ---------------------------------------------------------------------------
// Scratch (device globals; no allocation allowed). Plain row-major bf16 hi/lo.
// ---------------------------------------------------------------------------
__device__ __nv_bfloat16 g_vhi[TOK * EMB_], g_vlo[TOK * EMB_];
__device__ __nv_bfloat16 g_khi[TOK * EMB_], g_klo[TOK * EMB_];
__device__ __nv_bfloat16 g_qhi[TOK * EMB_], g_qlo[TOK * EMB_];
__device__ __nv_bfloat16 g_wvhi[EMB_ * EMB_], g_wvlo[EMB_ * EMB_];
__device__ __nv_bfloat16 g_wkhi[EMB_ * EMB_], g_wklo[EMB_ * EMB_];
__device__ __nv_bfloat16 g_wqhi[EMB_ * EMB_], g_wqlo[EMB_ * EMB_];
__device__ __nv_bfloat16 g_wohi[EMB_ * EMB_], g_wolo[EMB_ * EMB_];
__device__ __nv_bfloat16 g_ahi[TOK * EMB_], g_alo[TOK * EMB_];
__device__ float g_v[TOK * EMB_], g_k[TOK * EMB_], g_q[TOK * EMB_];

// ---------------------------------------------------------------------------
// Helpers (baseline PTX only: cp.async, ldmatrix, mma.sync — no 'a' features)
// ---------------------------------------------------------------------------
__device__ __forceinline__ uint32_t smem_u32(const void* p) {
    uint32_t a;
    asm("{ .reg .u64 t; cvta.to.shared.u64 t, %1; cvt.u32.u64 %0, t; }"
        : "=r"(a) : "l"(p));
    return a;
}

#define LDSM4(R, addr) \
    asm volatile("ldmatrix.sync.aligned.m8n8.x4.shared.b16 {%0,%1,%2,%3}, [%4];" \
        : "=r"((R)[0]), "=r"((R)[1]), "=r"((R)[2]), "=r"((R)[3]) : "r"(addr))

#define MMA16816(D, A, B0, B1) \
    asm volatile("mma.sync.aligned.m16n8k16.row.col.f32.bf16.bf16.f32 " \
        "{%0,%1,%2,%3}, {%4,%5,%6,%7}, {%8,%9}, {%0,%1,%2,%3};" \
        : "+f"((D)[0]), "+f"((D)[1]), "+f"((D)[2]), "+f"((D)[3]) \
        : "r"((A)[0]), "r"((A)[1]), "r"((A)[2]), "r"((A)[3]), "r"(B0), "r"(B1))

// ---------------------------------------------------------------------------
// Conversion: fp32 [nrows,1024] row-major -> bf16 hi/lo row-major.
// ---------------------------------------------------------------------------
__global__ __launch_bounds__(256)
void conv_split(const float* __restrict__ src, __nv_bfloat16* __restrict__ hi,
                __nv_bfloat16* __restrict__ lo, int nrows)
{
    const int gid = blockIdx.x * 256 + threadIdx.x;
    if (gid >= nrows * 128) return;
    const size_t e0 = (size_t)gid * 8;

    const float4* sp = (const float4*)(src + e0);
    float x[8];
    *(float4*)&x[0] = sp[0];
    *(float4*)&x[4] = sp[1];

    uint32_t hw[4], lw[4];
#pragma unroll
    for (int i = 0; i < 4; i++) {
        __nv_bfloat16 h0 = __float2bfloat16(x[2 * i]);
        __nv_bfloat16 h1 = __float2bfloat16(x[2 * i + 1]);
        __nv_bfloat16 l0 = __float2bfloat16(x[2 * i]     - __bfloat162float(h0));
        __nv_bfloat16 l1 = __float2bfloat16(x[2 * i + 1] - __bfloat162float(h1));
        hw[i] = (uint32_t)__bfloat16_as_ushort(h0) | ((uint32_t)__bfloat16_as_ushort(h1) << 16);
        lw[i] = (uint32_t)__bfloat16_as_ushort(l0) | ((uint32_t)__bfloat16_as_ushort(l1) << 16);
    }
    *(uint4*)(hi + e0) = make_uint4(hw[0], hw[1], hw[2], hw[3]);
    *(uint4*)(lo + e0) = make_uint4(lw[0], lw[1], lw[2], lw[3]);
}

// ---------------------------------------------------------------------------
// Split-bf16 HMMA GEMM: C[M,1024] = (Ah+Al)[M,1024] @ (Bh+Bl)[1024,1024]^T + bias
// (drops Al*Bl term). Tile 128x128, K-chunk 64, 2-stage cp.async pipeline.
// 8 warps in 4(M) x 2(N); warp tile 32m x 64n; mma.sync m16n8k16 bf16.
// SMEM rows padded to 144B (9 x 16B banks) -> conflict-free ldmatrix.
// ---------------------------------------------------------------------------
#define ROWB   144
#define TILEB  (128 * ROWB)     // 18432
#define STAGEB (4 * TILEB)      // 73728
#define SMEMB  (2 * STAGEB)     // 147456

__global__ __launch_bounds__(256, 1)
void gemm_hmma(const __nv_bfloat16* __restrict__ Ah, const __nv_bfloat16* __restrict__ Al,
               const __nv_bfloat16* __restrict__ Bh, const __nv_bfloat16* __restrict__ Bl,
               const float* __restrict__ bias, float* __restrict__ C)
{
    extern __shared__ char smem[];
    const uint32_t sb = smem_u32(smem);
    const int tid = threadIdx.x;
    const int wid = tid >> 5, lane = tid & 31;
    const int ntb = blockIdx.x, mtb = blockIdx.y;
    const int wm = wid >> 1, wn = wid & 1;

    const __nv_bfloat16* srcs[4] = {Ah, Al, Bh, Bl};

    // Issue one stage of cp.async: 4 tiles x 128 rows x 128B = 4096 x 16B chunks.
    auto load_stage = [&](int kc, int s) {
        const uint32_t dst0 = sb + s * STAGEB;
        const int k0 = kc * 64;
#pragma unroll
        for (int i = 0; i < 16; i++) {
            const int tile = i >> 2;                         // constant per unroll
            const int r = ((i & 3) * 32) + (tid >> 3);       // 0..127
            const int cc = tid & 7;                          // 16B chunk in row
            const int grow = ((tile < 2) ? mtb : ntb) * 128 + r;
            const char* g = (const char*)srcs[tile]
                          + ((size_t)grow * EMB_ + k0 + cc * 8) * 2;
            const uint32_t d = dst0 + tile * TILEB + r * ROWB + cc * 16;
            asm volatile("cp.async.cg.shared.global [%0], [%1], 16;"
                         :: "r"(d), "l"(g));
        }
        asm volatile("cp.async.commit_group;");
    };

    float acc[2][8][4];
#pragma unroll
    for (int a = 0; a < 2; a++)
#pragma unroll
        for (int b = 0; b < 8; b++)
#pragma unroll
            for (int c = 0; c < 4; c++) acc[a][b][c] = 0.0f;

    // Per-lane ldmatrix offsets (A: 16x16 from m-rows; B: 16n x 16k from n-rows)
    const uint32_t a_off = (uint32_t)(lane & 15) * ROWB + (lane >> 4) * 16;
    const uint32_t b_off = (uint32_t)(((lane >> 4) & 1) * 8 + (lane & 7)) * ROWB
                         + ((lane >> 3) & 1) * 16;

    load_stage(0, 0);
    load_stage(1, 1);

    for (int kc = 0; kc < 16; kc++) {
        if (kc < 14) asm volatile("cp.async.wait_group 1;");
        else         asm volatile("cp.async.wait_group 0;");
        __syncthreads();

        const uint32_t st = sb + (kc & 1) * STAGEB;
        const uint32_t aH = st + 0 * TILEB + (uint32_t)wm * 32 * ROWB + a_off;
        const uint32_t aL = st + 1 * TILEB + (uint32_t)wm * 32 * ROWB + a_off;
        const uint32_t bH = st + 2 * TILEB + (uint32_t)wn * 64 * ROWB + b_off;
        const uint32_t bL = st + 3 * TILEB + (uint32_t)wn * 64 * ROWB + b_off;

#pragma unroll
        for (int ks = 0; ks < 4; ks++) {
            uint32_t ah[2][4], al[2][4], bh[4][4], bl[4][4];
#pragma unroll
            for (int m2 = 0; m2 < 2; m2++) {
                LDSM4(ah[m2], aH + m2 * 16 * ROWB + ks * 32);
                LDSM4(al[m2], aL + m2 * 16 * ROWB + ks * 32);
            }
#pragma unroll
            for (int n2 = 0; n2 < 4; n2++) {
                LDSM4(bh[n2], bH + n2 * 16 * ROWB + ks * 32);
                LDSM4(bl[n2], bL + n2 * 16 * ROWB + ks * 32);
            }
#pragma unroll
            for (int m2 = 0; m2 < 2; m2++)
#pragma unroll
                for (int n2 = 0; n2 < 4; n2++) {
                    // hh
                    MMA16816(acc[m2][n2 * 2 + 0], ah[m2], bh[n2][0], bh[n2][1]);
                    MMA16816(acc[m2][n2 * 2 + 1], ah[m2], bh[n2][2], bh[n2][3]);
                    // hl
                    MMA16816(acc[m2][n2 * 2 + 0], ah[m2], bl[n2][0], bl[n2][1]);
                    MMA16816(acc[m2][n2 * 2 + 1], ah[m2], bl[n2][2], bl[n2][3]);
                    // lh
                    MMA16816(acc[m2][n2 * 2 + 0], al[m2], bh[n2][0], bh[n2][1]);
                    MMA16816(acc[m2][n2 * 2 + 1], al[m2], bh[n2][2], bh[n2][3]);
                }
        }
        __syncthreads();
        if (kc + 2 < 16) load_stage(kc + 2, kc & 1);
    }

    // Epilogue: acc -> gmem with bias. Thread t of warp: rows wm*32 + m2*16 +
    // lane/4 (+8), cols wn*64 + nt*8 + (lane%4)*2.
    const int rbase = mtb * 128 + wm * 32 + (lane >> 2);
    const int cbase = ntb * 128 + wn * 64 + (lane & 3) * 2;
#pragma unroll
    for (int m2 = 0; m2 < 2; m2++)
#pragma unroll
        for (int nt = 0; nt < 8; nt++) {
            const int col = cbase + nt * 8;
            const float b0 = bias[col], b1 = bias[col + 1];
            float* p0 = C + (size_t)(rbase + m2 * 16) * EMB_ + col;
            float* p1 = p0 + 8 * EMB_;
            float2 v0 = make_float2(acc[m2][nt][0] + b0, acc[m2][nt][1] + b1);
            float2 v1 = make_float2(acc[m2][nt][2] + b0, acc[m2][nt][3] + b1);
            *(float2*)p0 = v0;
            *(float2*)p1 = v1;
        }
}

// ---------------------------------------------------------------------------
// Per-token head-axis attention; emits bf16 hi/lo row-major for the output GEMM.
// ---------------------------------------------------------------------------
__global__ __launch_bounds__(256)
void attn_head_mix(const float* __restrict__ q, const float* __restrict__ k,
                   const float* __restrict__ v,
                   __nv_bfloat16* __restrict__ ohi, __nv_bfloat16* __restrict__ olo)
{
    __shared__ float sq[NHEAD][HDIM + 1];
    __shared__ float sk[NHEAD][HDIM + 1];
    __shared__ float sv[NHEAD][HDIM + 1];
    __shared__ float sa[NHEAD * NHEAD];

    const int t = blockIdx.x;
    const int tid = threadIdx.x;
    const size_t base = (size_t)t * EMB_;

#pragma unroll
    for (int e = tid; e < EMB_; e += 256) {
        const int h = e >> 6, d = e & 63;
        sq[h][d] = q[base + e];
        sk[h][d] = k[base + e];
        sv[h][d] = v[base + e];
    }
    __syncthreads();

    const int h = tid >> 4;
    const int g = tid & 15;
    float s = 0.0f;
#pragma unroll
    for (int d = 0; d < HDIM; d++) s = fmaf(sq[h][d], sk[g][d], s);
    s *= 0.125f;

    float m = s;
#pragma unroll
    for (int o = 8; o > 0; o >>= 1)
        m = fmaxf(m, __shfl_xor_sync(0xffffffffu, m, o, 16));
    const float e = __expf(s - m);
    float sum = e;
#pragma unroll
    for (int o = 8; o > 0; o >>= 1)
        sum += __shfl_xor_sync(0xffffffffu, sum, o, 16);
    sa[h * 16 + g] = e / sum;
    __syncthreads();

    const int ho = tid >> 4;
    const int d0 = (tid & 15) * 4;
    float o4[4] = {0.f, 0.f, 0.f, 0.f};
#pragma unroll
    for (int gg = 0; gg < NHEAD; gg++) {
        const float a = sa[ho * 16 + gg];
        o4[0] = fmaf(a, sv[gg][d0 + 0], o4[0]);
        o4[1] = fmaf(a, sv[gg][d0 + 1], o4[1]);
        o4[2] = fmaf(a, sv[gg][d0 + 2], o4[2]);
        o4[3] = fmaf(a, sv[gg][d0 + 3], o4[3]);
    }

    ushort4 hv, lv;
    __nv_bfloat16 hb;
    hb = __float2bfloat16(o4[0]); hv.x = __bfloat16_as_ushort(hb);
    lv.x = __bfloat16_as_ushort(__float2bfloat16(o4[0] - __bfloat162float(hb)));
    hb = __float2bfloat16(o4[1]); hv.y = __bfloat16_as_ushort(hb);
    lv.y = __bfloat16_as_ushort(__float2bfloat16(o4[1] - __bfloat162float(hb)));
    hb = __float2bfloat16(o4[2]); hv.z = __bfloat16_as_ushort(hb);
    lv.z = __bfloat16_as_ushort(__float2bfloat16(o4[2] - __bfloat162float(hb)));
    hb = __float2bfloat16(o4[3]); hv.w = __bfloat16_as_ushort(hb);
    lv.w = __bfloat16_as_ushort(__float2bfloat16(o4[3] - __bfloat162float(hb)));
    *(ushort4*)(ohi + base + ho * HDIM + d0) = hv;
    *(ushort4*)(olo + base + ho * HDIM + d0) = lv;
}

// ---------------------------------------------------------------------------
// Launch
// ---------------------------------------------------------------------------
extern "C" void kernel_launch(void* const* d_in, const int* in_sizes, int n_in,
                              void* d_out, int out_size)
{
    const float* values = (const float*)d_in[0];
    const float* keys   = (const float*)d_in[1];
    const float* query  = (const float*)d_in[2];
    const float* Wv = (const float*)d_in[3];
    const float* bv = (const float*)d_in[4];
    const float* Wk = (const float*)d_in[5];
    const float* bk = (const float*)d_in[6];
    const float* Wq = (const float*)d_in[7];
    const float* bq = (const float*)d_in[8];
    const float* Wo = (const float*)d_in[9];
    const float* bo = (const float*)d_in[10];
    float* out = (float*)d_out;

    static bool attr_set = false;
    if (!attr_set) {
        cudaFuncSetAttribute(gemm_hmma,
                             cudaFuncAttributeMaxDynamicSharedMemorySize, SMEMB);
        attr_set = true;
    }

    __nv_bfloat16 *vhi, *vlo, *khi, *klo, *qhi, *qlo;
    __nv_bfloat16 *wvhi, *wvlo, *wkhi, *wklo, *wqhi, *wqlo, *wohi, *wolo;
    __nv_bfloat16 *ahi, *alo;
    float *gv, *gk, *gq;
    cudaGetSymbolAddress((void**)&vhi, g_vhi);   cudaGetSymbolAddress((void**)&vlo, g_vlo);
    cudaGetSymbolAddress((void**)&khi, g_khi);   cudaGetSymbolAddress((void**)&klo, g_klo);
    cudaGetSymbolAddress((void**)&qhi, g_qhi);   cudaGetSymbolAddress((void**)&qlo, g_qlo);
    cudaGetSymbolAddress((void**)&wvhi, g_wvhi); cudaGetSymbolAddress((void**)&wvlo, g_wvlo);
    cudaGetSymbolAddress((void**)&wkhi, g_wkhi); cudaGetSymbolAddress((void**)&wklo, g_wklo);
    cudaGetSymbolAddress((void**)&wqhi, g_wqhi); cudaGetSymbolAddress((void**)&wqlo, g_wqlo);
    cudaGetSymbolAddress((void**)&wohi, g_wohi); cudaGetSymbolAddress((void**)&wolo, g_wolo);
    cudaGetSymbolAddress((void**)&ahi, g_ahi);   cudaGetSymbolAddress((void**)&alo, g_alo);
    cudaGetSymbolAddress((void**)&gv, g_v);
    cudaGetSymbolAddress((void**)&gk, g_k);
    cudaGetSymbolAddress((void**)&gq, g_q);

    conv_split<<<TOK * 128 / 256, 256>>>(values, vhi, vlo, TOK);
    conv_split<<<TOK * 128 / 256, 256>>>(keys,   khi, klo, TOK);
    conv_split<<<TOK * 128 / 256, 256>>>(query,  qhi, qlo, TOK);
    conv_split<<<EMB_ * 128 / 256, 256>>>(Wv, wvhi, wvlo, EMB_);
    conv_split<<<EMB_ * 128 / 256, 256>>>(Wk, wkhi, wklo, EMB_);
    conv_split<<<EMB_ * 128 / 256, 256>>>(Wq, wqhi, wqlo, EMB_);
    conv_split<<<EMB_ * 128 / 256, 256>>>(Wo, wohi, wolo, EMB_);

    dim3 ggrid(EMB_ / 128, TOK / 128);   // (8, 64)
    gemm_hmma<<<ggrid, 256, SMEMB>>>(vhi, vlo, wvhi, wvlo, bv, gv);
    gemm_hmma<<<ggrid, 256, SMEMB>>>(khi, klo, wkhi, wklo, bk, gk);
    gemm_hmma<<<ggrid, 256, SMEMB>>>(qhi, qlo, wqhi, wqlo, bq, gq);

    attn_head_mix<<<TOK, 256>>>(gq, gk, gv, ahi, alo);

    gemm_hmma<<<ggrid, 256, SMEMB>>>(ahi, alo, wohi, wolo, bo, out);
}

// round 4
// speedup vs baseline: 3.0146x; 1.2603x over previous
#include <cuda_runtime.h>
#include <cuda_fp16.h>
#include <cstdint>

// Problem constants (B=4, S=2048, EMB=1024, HEADS=16, HEAD_DIM=64)
#define TOK   8192
#define EMB_  1024
#define NHEAD 16
#define HDIM  64

// ---------------------------------------------------------------------------
// Scratch (device globals; no allocation allowed). Row-major fp16 hi/lo.
// ---------------------------------------------------------------------------
__device__ __half g_vhi[TOK * EMB_], g_vlo[TOK * EMB_];
__device__ __half g_khi[TOK * EMB_], g_klo[TOK * EMB_];
__device__ __half g_qhi[TOK * EMB_], g_qlo[TOK * EMB_];
__device__ __half g_wvhi[EMB_ * EMB_];                       // 2-term: hi only
__device__ __half g_wkhi[EMB_ * EMB_], g_wklo[EMB_ * EMB_];  // 3-term
__device__ __half g_wqhi[EMB_ * EMB_], g_wqlo[EMB_ * EMB_];  // 3-term
__device__ __half g_wohi[EMB_ * EMB_];                       // 2-term: hi only
__device__ __half g_ahi[TOK * EMB_], g_alo[TOK * EMB_];
__device__ float g_v[TOK * EMB_], g_k[TOK * EMB_], g_q[TOK * EMB_];

// ---------------------------------------------------------------------------
// Helpers (baseline PTX only: cp.async, ldmatrix, mma.sync)
// ---------------------------------------------------------------------------
__device__ __forceinline__ uint32_t smem_u32(const void* p) {
    uint32_t a;
    asm("{ .reg .u64 t; cvta.to.shared.u64 t, %1; cvt.u32.u64 %0, t; }"
        : "=r"(a) : "l"(p));
    return a;
}

#define LDSM4(R, addr) \
    asm volatile("ldmatrix.sync.aligned.m8n8.x4.shared.b16 {%0,%1,%2,%3}, [%4];" \
        : "=r"((R)[0]), "=r"((R)[1]), "=r"((R)[2]), "=r"((R)[3]) : "r"(addr))

#define MMA16816(D, A, B0, B1) \
    asm volatile("mma.sync.aligned.m16n8k16.row.col.f32.f16.f16.f32 " \
        "{%0,%1,%2,%3}, {%4,%5,%6,%7}, {%8,%9}, {%0,%1,%2,%3};" \
        : "+f"((D)[0]), "+f"((D)[1]), "+f"((D)[2]), "+f"((D)[3]) \
        : "r"((A)[0]), "r"((A)[1]), "r"((A)[2]), "r"((A)[3]), "r"(B0), "r"(B1))

// ---------------------------------------------------------------------------
// Conversions: fp32 -> fp16 hi/lo (split), or hi only (round).
// ---------------------------------------------------------------------------
__global__ __launch_bounds__(256)
void conv_split(const float* __restrict__ src, __half* __restrict__ hi,
                __half* __restrict__ lo, int nrows)
{
    const int gid = blockIdx.x * 256 + threadIdx.x;
    if (gid >= nrows * 128) return;
    const size_t e0 = (size_t)gid * 8;
    const float4* sp = (const float4*)(src + e0);
    float x[8];
    *(float4*)&x[0] = sp[0];
    *(float4*)&x[4] = sp[1];

    uint32_t hw[4], lw[4];
#pragma unroll
    for (int i = 0; i < 4; i++) {
        __half h0 = __float2half_rn(x[2 * i]);
        __half h1 = __float2half_rn(x[2 * i + 1]);
        __half l0 = __float2half_rn(x[2 * i]     - __half2float(h0));
        __half l1 = __float2half_rn(x[2 * i + 1] - __half2float(h1));
        hw[i] = (uint32_t)__half_as_ushort(h0) | ((uint32_t)__half_as_ushort(h1) << 16);
        lw[i] = (uint32_t)__half_as_ushort(l0) | ((uint32_t)__half_as_ushort(l1) << 16);
    }
    *(uint4*)(hi + e0) = make_uint4(hw[0], hw[1], hw[2], hw[3]);
    *(uint4*)(lo + e0) = make_uint4(lw[0], lw[1], lw[2], lw[3]);
}

__global__ __launch_bounds__(256)
void conv_round(const float* __restrict__ src, __half* __restrict__ hi, int nrows)
{
    const int gid = blockIdx.x * 256 + threadIdx.x;
    if (gid >= nrows * 128) return;
    const size_t e0 = (size_t)gid * 8;
    const float4* sp = (const float4*)(src + e0);
    float x[8];
    *(float4*)&x[0] = sp[0];
    *(float4*)&x[4] = sp[1];
    uint32_t hw[4];
#pragma unroll
    for (int i = 0; i < 4; i++) {
        __half h0 = __float2half_rn(x[2 * i]);
        __half h1 = __float2half_rn(x[2 * i + 1]);
        hw[i] = (uint32_t)__half_as_ushort(h0) | ((uint32_t)__half_as_ushort(h1) << 16);
    }
    *(uint4*)(hi + e0) = make_uint4(hw[0], hw[1], hw[2], hw[3]);
}

// ---------------------------------------------------------------------------
// Split-fp16 HMMA GEMM core: C[M,1024] = A @ B^T + bias
//   NTERMS==3: C ~= Ah·Bh + Ah·Bl + Al·Bh   (err ~1e-6)
//   NTERMS==2: C ~= (Ah+Al)·Bh              (err ~1.2e-4, B rounded)
// Tile 128x128, K-chunk 64, 2-stage cp.async pipeline, 8 warps (4m x 2n).
// SMEM rows padded to 144B -> conflict-free ldmatrix.
// ---------------------------------------------------------------------------
#define ROWB   144
#define TILEB  (128 * ROWB)       // 18432

template <int NTERMS>
__device__ __forceinline__
void gemm_core(const __half* __restrict__ Ah, const __half* __restrict__ Al,
               const __half* __restrict__ Bh, const __half* __restrict__ Bl,
               const float* __restrict__ bias, float* __restrict__ C,
               char* smem)
{
    constexpr int NT = (NTERMS == 3) ? 4 : 3;     // tiles per stage
    constexpr int STAGEB = NT * TILEB;

    const uint32_t sb = smem_u32(smem);
    const int tid = threadIdx.x;
    const int wid = tid >> 5, lane = tid & 31;
    const int ntb = blockIdx.x, mtb = blockIdx.y;
    const int wm = wid >> 1, wn = wid & 1;

    const __half* srcs[4] = {Ah, Al, Bh, Bl};

    auto load_stage = [&](int kc, int s) {
        const uint32_t dst0 = sb + s * STAGEB;
        const int k0 = kc * 64;
#pragma unroll
        for (int i = 0; i < NT * 4; i++) {
            const int tile = i >> 2;
            const int r = ((i & 3) * 32) + (tid >> 3);
            const int cc = tid & 7;
            const int grow = ((tile < 2) ? mtb : ntb) * 128 + r;
            const char* g = (const char*)srcs[tile]
                          + ((size_t)grow * EMB_ + k0 + cc * 8) * 2;
            const uint32_t d = dst0 + tile * TILEB + r * ROWB + cc * 16;
            asm volatile("cp.async.cg.shared.global [%0], [%1], 16;"
                         :: "r"(d), "l"(g));
        }
        asm volatile("cp.async.commit_group;");
    };

    float acc[2][8][4];
#pragma unroll
    for (int a = 0; a < 2; a++)
#pragma unroll
        for (int b = 0; b < 8; b++)
#pragma unroll
            for (int c = 0; c < 4; c++) acc[a][b][c] = 0.0f;

    const uint32_t a_off = (uint32_t)(lane & 15) * ROWB + (lane >> 4) * 16;
    const uint32_t b_off = (uint32_t)(((lane >> 4) & 1) * 8 + (lane & 7)) * ROWB
                         + ((lane >> 3) & 1) * 16;

    load_stage(0, 0);
    load_stage(1, 1);

    for (int kc = 0; kc < 16; kc++) {
        if (kc < 14) asm volatile("cp.async.wait_group 1;");
        else         asm volatile("cp.async.wait_group 0;");
        __syncthreads();

        const uint32_t st = sb + (kc & 1) * STAGEB;
        const uint32_t aH = st + 0 * TILEB + (uint32_t)wm * 32 * ROWB + a_off;
        const uint32_t aL = st + 1 * TILEB + (uint32_t)wm * 32 * ROWB + a_off;
        const uint32_t bH = st + 2 * TILEB + (uint32_t)wn * 64 * ROWB + b_off;
        const uint32_t bL = st + 3 * TILEB + (uint32_t)wn * 64 * ROWB + b_off;

#pragma unroll
        for (int ks = 0; ks < 4; ks++) {
            uint32_t ah[2][4], al[2][4], bh[4][4], bl[4][4];
#pragma unroll
            for (int m2 = 0; m2 < 2; m2++) {
                LDSM4(ah[m2], aH + m2 * 16 * ROWB + ks * 32);
                LDSM4(al[m2], aL + m2 * 16 * ROWB + ks * 32);
            }
#pragma unroll
            for (int n2 = 0; n2 < 4; n2++) {
                LDSM4(bh[n2], bH + n2 * 16 * ROWB + ks * 32);
                if (NTERMS == 3) LDSM4(bl[n2], bL + n2 * 16 * ROWB + ks * 32);
            }
#pragma unroll
            for (int m2 = 0; m2 < 2; m2++)
#pragma unroll
                for (int n2 = 0; n2 < 4; n2++) {
                    MMA16816(acc[m2][n2 * 2 + 0], ah[m2], bh[n2][0], bh[n2][1]);
                    MMA16816(acc[m2][n2 * 2 + 1], ah[m2], bh[n2][2], bh[n2][3]);
                    MMA16816(acc[m2][n2 * 2 + 0], al[m2], bh[n2][0], bh[n2][1]);
                    MMA16816(acc[m2][n2 * 2 + 1], al[m2], bh[n2][2], bh[n2][3]);
                    if (NTERMS == 3) {
                        MMA16816(acc[m2][n2 * 2 + 0], ah[m2], bl[n2][0], bl[n2][1]);
                        MMA16816(acc[m2][n2 * 2 + 1], ah[m2], bl[n2][2], bl[n2][3]);
                    }
                }
        }
        __syncthreads();
        if (kc + 2 < 16) load_stage(kc + 2, kc & 1);
    }

    const int rbase = mtb * 128 + wm * 32 + (lane >> 2);
    const int cbase = ntb * 128 + wn * 64 + (lane & 3) * 2;
#pragma unroll
    for (int m2 = 0; m2 < 2; m2++)
#pragma unroll
        for (int nt2 = 0; nt2 < 8; nt2++) {
            const int col = cbase + nt2 * 8;
            const float b0 = bias[col], b1 = bias[col + 1];
            float* p0 = C + (size_t)(rbase + m2 * 16) * EMB_ + col;
            float* p1 = p0 + 8 * EMB_;
            *(float2*)p0 = make_float2(acc[m2][nt2][0] + b0, acc[m2][nt2][1] + b1);
            *(float2*)p1 = make_float2(acc[m2][nt2][2] + b0, acc[m2][nt2][3] + b1);
        }
}

// Merged Q/K/V projection launch: z=0 Q (3-term), z=1 K (3-term), z=2 V (2-term)
struct QKVArgs {
    const __half* ah[3];
    const __half* al[3];
    const __half* bh[3];
    const __half* bl[3];
    const float*  bias[3];
    float*        c[3];
};

__global__ __launch_bounds__(256, 1)
void gemm_qkv(QKVArgs a)
{
    extern __shared__ char smem[];
    const int z = blockIdx.z;
    if (z == 2)
        gemm_core<2>(a.ah[2], a.al[2], a.bh[2], nullptr, a.bias[2], a.c[2], smem);
    else
        gemm_core<3>(a.ah[z], a.al[z], a.bh[z], a.bl[z], a.bias[z], a.c[z], smem);
}

__global__ __launch_bounds__(256, 1)
void gemm_o(const __half* __restrict__ ah, const __half* __restrict__ al,
            const __half* __restrict__ bh, const float* __restrict__ bias,
            float* __restrict__ c)
{
    extern __shared__ char smem[];
    gemm_core<2>(ah, al, bh, nullptr, bias, c, smem);
}

// ---------------------------------------------------------------------------
// Per-token head-axis attention (fp32 in, fp16 hi/lo out).
// float4 gmem loads; K transposed in smem for conflict-free score reads.
// ---------------------------------------------------------------------------
__global__ __launch_bounds__(256)
void attn_head_mix(const float* __restrict__ q, const float* __restrict__ k,
                   const float* __restrict__ v,
                   __half* __restrict__ ohi, __half* __restrict__ olo)
{
    __shared__ float sq[NHEAD][68];    // padded, 16B-aligned rows
    __shared__ float skT[HDIM][17];    // transposed K
    __shared__ float sv[NHEAD][68];
    __shared__ float sa[NHEAD * NHEAD];

    const int t = blockIdx.x;
    const int tid = threadIdx.x;
    const size_t base = (size_t)t * EMB_;

    // Load 4 consecutive floats per thread per array (fully coalesced LDG.128).
    {
        const int e0 = tid * 4;
        const int h = e0 >> 6, d0 = e0 & 63;
        float4 q4 = *(const float4*)(q + base + e0);
        float4 k4 = *(const float4*)(k + base + e0);
        float4 v4 = *(const float4*)(v + base + e0);
        *(float4*)&sq[h][d0] = q4;
        *(float4*)&sv[h][d0] = v4;
        skT[d0 + 0][h] = k4.x;
        skT[d0 + 1][h] = k4.y;
        skT[d0 + 2][h] = k4.z;
        skT[d0 + 3][h] = k4.w;
    }
    __syncthreads();

    // One thread per (h,g) score.
    const int h = tid >> 4;
    const int g = tid & 15;
    float s = 0.0f;
#pragma unroll
    for (int d = 0; d < HDIM; d++) s = fmaf(sq[h][d], skT[d][g], s);
    s *= 0.125f;

    float m = s;
#pragma unroll
    for (int o = 8; o > 0; o >>= 1)
        m = fmaxf(m, __shfl_xor_sync(0xffffffffu, m, o, 16));
    const float e = __expf(s - m);
    float sum = e;
#pragma unroll
    for (int o = 8; o > 0; o >>= 1)
        sum += __shfl_xor_sync(0xffffffffu, sum, o, 16);
    sa[h * 16 + g] = e / sum;
    __syncthreads();

    // out[ho][d0..d0+3]; coalesced 8B hi/lo stores.
    const int ho = tid >> 4;
    const int d0 = (tid & 15) * 4;
    float o4[4] = {0.f, 0.f, 0.f, 0.f};
#pragma unroll
    for (int gg = 0; gg < NHEAD; gg++) {
        const float a = sa[ho * 16 + gg];
        float4 vv = *(const float4*)&sv[gg][d0];
        o4[0] = fmaf(a, vv.x, o4[0]);
        o4[1] = fmaf(a, vv.y, o4[1]);
        o4[2] = fmaf(a, vv.z, o4[2]);
        o4[3] = fmaf(a, vv.w, o4[3]);
    }

    ushort4 hv, lv;
    __half hb;
    hb = __float2half_rn(o4[0]); hv.x = __half_as_ushort(hb);
    lv.x = __half_as_ushort(__float2half_rn(o4[0] - __half2float(hb)));
    hb = __float2half_rn(o4[1]); hv.y = __half_as_ushort(hb);
    lv.y = __half_as_ushort(__float2half_rn(o4[1] - __half2float(hb)));
    hb = __float2half_rn(o4[2]); hv.z = __half_as_ushort(hb);
    lv.z = __half_as_ushort(__float2half_rn(o4[2] - __half2float(hb)));
    hb = __float2half_rn(o4[3]); hv.w = __half_as_ushort(hb);
    lv.w = __half_as_ushort(__float2half_rn(o4[3] - __half2float(hb)));
    *(ushort4*)(ohi + base + ho * HDIM + d0) = hv;
    *(ushort4*)(olo + base + ho * HDIM + d0) = lv;
}

// ---------------------------------------------------------------------------
// Launch
// ---------------------------------------------------------------------------
extern "C" void kernel_launch(void* const* d_in, const int* in_sizes, int n_in,
                              void* d_out, int out_size)
{
    const float* values = (const float*)d_in[0];
    const float* keys   = (const float*)d_in[1];
    const float* query  = (const float*)d_in[2];
    const float* Wv = (const float*)d_in[3];
    const float* bv = (const float*)d_in[4];
    const float* Wk = (const float*)d_in[5];
    const float* bk = (const float*)d_in[6];
    const float* Wq = (const float*)d_in[7];
    const float* bq = (const float*)d_in[8];
    const float* Wo = (const float*)d_in[9];
    const float* bo = (const float*)d_in[10];
    float* out = (float*)d_out;

    static bool attr_set = false;
    if (!attr_set) {
        cudaFuncSetAttribute(gemm_qkv,
                             cudaFuncAttributeMaxDynamicSharedMemorySize, 8 * TILEB);
        cudaFuncSetAttribute(gemm_o,
                             cudaFuncAttributeMaxDynamicSharedMemorySize, 6 * TILEB);
        attr_set = true;
    }

    __half *vhi, *vlo, *khi, *klo, *qhi, *qlo;
    __half *wvhi, *wkhi, *wklo, *wqhi, *wqlo, *wohi;
    __half *ahi, *alo;
    float *gv, *gk, *gq;
    cudaGetSymbolAddress((void**)&vhi, g_vhi);   cudaGetSymbolAddress((void**)&vlo, g_vlo);
    cudaGetSymbolAddress((void**)&khi, g_khi);   cudaGetSymbolAddress((void**)&klo, g_klo);
    cudaGetSymbolAddress((void**)&qhi, g_qhi);   cudaGetSymbolAddress((void**)&qlo, g_qlo);
    cudaGetSymbolAddress((void**)&wvhi, g_wvhi);
    cudaGetSymbolAddress((void**)&wkhi, g_wkhi); cudaGetSymbolAddress((void**)&wklo, g_wklo);
    cudaGetSymbolAddress((void**)&wqhi, g_wqhi); cudaGetSymbolAddress((void**)&wqlo, g_wqlo);
    cudaGetSymbolAddress((void**)&wohi, g_wohi);
    cudaGetSymbolAddress((void**)&ahi, g_ahi);   cudaGetSymbolAddress((void**)&alo, g_alo);
    cudaGetSymbolAddress((void**)&gv, g_v);
    cudaGetSymbolAddress((void**)&gk, g_k);
    cudaGetSymbolAddress((void**)&gq, g_q);

    // Conversions
    conv_split<<<TOK * 128 / 256, 256>>>(values, vhi, vlo, TOK);
    conv_split<<<TOK * 128 / 256, 256>>>(keys,   khi, klo, TOK);
    conv_split<<<TOK * 128 / 256, 256>>>(query,  qhi, qlo, TOK);
    conv_split<<<EMB_ * 128 / 256, 256>>>(Wk, wkhi, wklo, EMB_);
    conv_split<<<EMB_ * 128 / 256, 256>>>(Wq, wqhi, wqlo, EMB_);
    conv_round<<<EMB_ * 128 / 256, 256>>>(Wv, wvhi, EMB_);
    conv_round<<<EMB_ * 128 / 256, 256>>>(Wo, wohi, EMB_);

    // Merged Q/K/V projections
    QKVArgs a;
    a.ah[0] = qhi; a.al[0] = qlo; a.bh[0] = wqhi; a.bl[0] = wqlo; a.bias[0] = bq; a.c[0] = gq;
    a.ah[1] = khi; a.al[1] = klo; a.bh[1] = wkhi; a.bl[1] = wklo; a.bias[1] = bk; a.c[1] = gk;
    a.ah[2] = vhi; a.al[2] = vlo; a.bh[2] = wvhi; a.bl[2] = nullptr; a.bias[2] = bv; a.c[2] = gv;
    dim3 ggrid(EMB_ / 128, TOK / 128, 3);
    gemm_qkv<<<ggrid, 256, 8 * TILEB>>>(a);

    attn_head_mix<<<TOK, 256>>>(gq, gk, gv, ahi, alo);

    dim3 ogrid(EMB_ / 128, TOK / 128);
    gemm_o<<<ogrid, 256, 6 * TILEB>>>(ahi, alo, wohi, bo, out);
}

// round 5
// speedup vs baseline: 3.6579x; 1.2134x over previous
#include <cuda_runtime.h>
#include <cuda_fp16.h>
#include <cstdint>

// Problem constants (B=4, S=2048, EMB=1024, HEADS=16, HEAD_DIM=64)
#define TOK   8192
#define EMB_  1024
#define NHEAD 16
#define HDIM  64
#define TILEB 16384          // one 128x128-byte (128 rows x 64 fp16) tile

// ---------------------------------------------------------------------------
// Scratch (device globals). Tiled-swizzled fp16:
// element (row, col) -> tile (row>>7, col>>6), inside: byte
//   (row&127)*128 + (((col&63)>>3) ^ (row&7))*16 + (col&7)*2
// Tile id = (rowTile * 16 + colTile) * 16384.
// ---------------------------------------------------------------------------
__device__ __half g_vhi[TOK * EMB_], g_vlo[TOK * EMB_];
__device__ __half g_khi[TOK * EMB_], g_klo[TOK * EMB_];
__device__ __half g_qhi[TOK * EMB_], g_qlo[TOK * EMB_];
__device__ __half g_wvhi[EMB_ * EMB_];                       // 2-term
__device__ __half g_wkhi[EMB_ * EMB_], g_wklo[EMB_ * EMB_];  // 3-term
__device__ __half g_wqhi[EMB_ * EMB_], g_wqlo[EMB_ * EMB_];  // 3-term
__device__ __half g_wohi[EMB_ * EMB_];                       // 2-term
__device__ __half g_ahi[TOK * EMB_], g_alo[TOK * EMB_];
__device__ float g_v[TOK * EMB_], g_k[TOK * EMB_], g_q[TOK * EMB_];

// ---------------------------------------------------------------------------
// PTX helpers (baseline sm_90-level PTX only; verified non-'a' accepted)
// ---------------------------------------------------------------------------
__device__ __forceinline__ uint32_t smem_u32(const void* p) {
    uint32_t a;
    asm("{ .reg .u64 t; cvta.to.shared.u64 t, %1; cvt.u32.u64 %0, t; }"
        : "=r"(a) : "l"(p));
    return a;
}

#define MBAR_INIT(addr, cnt) \
    asm volatile("mbarrier.init.shared.b64 [%0], %1;" :: "r"(addr), "r"(cnt) : "memory")
#define MBAR_EXPECT_TX(addr, bytes) \
    asm volatile("mbarrier.arrive.expect_tx.shared.b64 _, [%0], %1;" \
                 :: "r"(addr), "r"(bytes) : "memory")
#define MBAR_WAIT(addr, parity) do { \
    uint32_t _m = (addr), _p = (parity), _done; \
    asm volatile("{ .reg .pred p; mbarrier.try_wait.parity.acquire.cta.shared::cta.b64 p, [%1], %2; selp.b32 %0, 1, 0, p; }" \
                 : "=r"(_done) : "r"(_m), "r"(_p) : "memory"); \
    if (!_done) { \
        asm volatile("{ .reg .pred P1; WL_%=: mbarrier.try_wait.parity.acquire.cta.shared::cta.b64 P1, [%0], %1, 0x989680; @P1 bra.uni WD_%=; bra.uni WL_%=; WD_%=: }" \
                     :: "r"(_m), "r"(_p) : "memory"); \
    } \
} while (0)

__device__ __forceinline__ void bulk_g2s(uint32_t dst, const void* src,
                                         uint32_t bytes, uint32_t mbar) {
    asm volatile(
        "cp.async.bulk.shared::cluster.global.mbarrier::complete_tx::bytes [%0], [%1], %2, [%3];"
        :: "r"(dst), "l"(src), "r"(bytes), "r"(mbar) : "memory");
}

#define LDSM4(R, addr) \
    asm volatile("ldmatrix.sync.aligned.m8n8.x4.shared.b16 {%0,%1,%2,%3}, [%4];" \
        : "=r"((R)[0]), "=r"((R)[1]), "=r"((R)[2]), "=r"((R)[3]) : "r"(addr))

#define MMA16816(D, A, B0, B1) \
    asm volatile("mma.sync.aligned.m16n8k16.row.col.f32.f16.f16.f32 " \
        "{%0,%1,%2,%3}, {%4,%5,%6,%7}, {%8,%9}, {%0,%1,%2,%3};" \
        : "+f"((D)[0]), "+f"((D)[1]), "+f"((D)[2]), "+f"((D)[3]) \
        : "r"((A)[0]), "r"((A)[1]), "r"((A)[2]), "r"((A)[3]), "r"(B0), "r"(B1))

// ---------------------------------------------------------------------------
// Conversions: fp32 row-major -> fp16 hi/lo in tiled-swizzled layout.
// One thread per 16B chunk (8 cols).
// ---------------------------------------------------------------------------
__device__ __forceinline__ void split_store(const float* __restrict__ src,
                                            __half* __restrict__ hi,
                                            __half* __restrict__ lo, int gid)
{
    const int row = gid >> 7;
    const int chunk = gid & 127;          // 16B chunk within row (1024 cols = 128)
    const int col0 = chunk << 3;
    const int kc = col0 >> 6;
    const int c16 = (col0 >> 3) & 7;

    const float4* sp = (const float4*)(src + (size_t)row * EMB_ + col0);
    float x[8];
    *(float4*)&x[0] = sp[0];
    *(float4*)&x[4] = sp[1];

    uint32_t hw[4], lw[4];
#pragma unroll
    for (int i = 0; i < 4; i++) {
        __half h0 = __float2half_rn(x[2 * i]);
        __half h1 = __float2half_rn(x[2 * i + 1]);
        hw[i] = (uint32_t)__half_as_ushort(h0) | ((uint32_t)__half_as_ushort(h1) << 16);
        if (lo) {
            __half l0 = __float2half_rn(x[2 * i]     - __half2float(h0));
            __half l1 = __float2half_rn(x[2 * i + 1] - __half2float(h1));
            lw[i] = (uint32_t)__half_as_ushort(l0) | ((uint32_t)__half_as_ushort(l1) << 16);
        }
    }
    const size_t off = (((size_t)(row >> 7) * 16 + kc) << 14)
                     + (row & 127) * 128 + ((c16 ^ (row & 7)) << 4);
    *(uint4*)((char*)hi + off) = make_uint4(hw[0], hw[1], hw[2], hw[3]);
    if (lo)
        *(uint4*)((char*)lo + off) = make_uint4(lw[0], lw[1], lw[2], lw[3]);
}

struct ConvArgs {
    const float* src[4];
    __half* hi[4];
    __half* lo[4];     // null -> round-only
};

__global__ __launch_bounds__(256)
void conv_act(ConvArgs a)   // grid (4096, 3): activations, all split
{
    const int z = blockIdx.y;
    const int gid = blockIdx.x * 256 + threadIdx.x;
    split_store(a.src[z], a.hi[z], a.lo[z], gid);
}

__global__ __launch_bounds__(256)
void conv_w(ConvArgs a)     // grid (512, 4): Wq,Wk split; Wv,Wo round
{
    const int z = blockIdx.y;
    const int gid = blockIdx.x * 256 + threadIdx.x;
    split_store(a.src[z], a.hi[z], a.lo[z], gid);
}

// ---------------------------------------------------------------------------
// Split-fp16 HMMA GEMM with bulk-copy pipeline.
//   NTERMS==3: C ~= Ah·Bh + Ah·Bl + Al·Bh
//   NTERMS==2: C ~= (Ah+Al)·Bh
// Tile 128x128, K-chunk 64, 2-stage double buffer, 8 warps (4m x 2n).
// Stage = NT x 16KB tiles loaded with one bulk copy each by thread 0.
// ---------------------------------------------------------------------------
template <int NTERMS>
__device__ __forceinline__
void gemm_core(const __half* __restrict__ Ah, const __half* __restrict__ Al,
               const __half* __restrict__ Bh, const __half* __restrict__ Bl,
               const float* __restrict__ bias, float* __restrict__ C,
               char* smem)
{
    constexpr int NT = (NTERMS == 3) ? 4 : 3;
    constexpr uint32_t STAGEB = NT * TILEB;

    const uint32_t sb = smem_u32(smem);          // [0,64): barriers; 1024+: tiles
    const int tid = threadIdx.x;
    const int wid = tid >> 5, lane = tid & 31;
    const int ntb = blockIdx.x, mtb = blockIdx.y;
    const int wm = wid >> 1, wn = wid & 1;

    if (tid == 0) {
        MBAR_INIT(sb + 0, 1);
        MBAR_INIT(sb + 8, 1);
    }
    __syncthreads();

    const uint32_t st0 = sb + 1024;
    const char* aH = (const char*)Ah + ((size_t)mtb * 16 << 14);
    const char* aL = (const char*)Al + ((size_t)mtb * 16 << 14);
    const char* bH = (const char*)Bh + ((size_t)ntb * 16 << 14);
    const char* bL = (NTERMS == 3) ? (const char*)Bl + ((size_t)ntb * 16 << 14) : nullptr;

    auto load_stage = [&](int kc, int s) {
        const uint32_t full = sb + 8 * s;
        MBAR_EXPECT_TX(full, NT * TILEB);
        const uint32_t d = st0 + s * STAGEB;
        const size_t o = (size_t)kc << 14;
        bulk_g2s(d + 0 * TILEB, aH + o, TILEB, full);
        bulk_g2s(d + 1 * TILEB, aL + o, TILEB, full);
        bulk_g2s(d + 2 * TILEB, bH + o, TILEB, full);
        if (NTERMS == 3) bulk_g2s(d + 3 * TILEB, bL + o, TILEB, full);
    };

    if (tid == 0) {
        load_stage(0, 0);
        load_stage(1, 1);
    }

    float acc[2][8][4];
#pragma unroll
    for (int a = 0; a < 2; a++)
#pragma unroll
        for (int b = 0; b < 8; b++)
#pragma unroll
            for (int c = 0; c < 4; c++) acc[a][b][c] = 0.0f;

    // Per-lane swizzled ldmatrix addressing.
    const uint32_t la7 = lane & 7;
    const uint32_t a_row = (uint32_t)(wm * 32 + (lane & 15)) * 128;
    const uint32_t a_sel = (lane >> 4);            // chunk parity within 32B
    const uint32_t b_row = (uint32_t)(wn * 64 + ((lane >> 4) & 1) * 8 + (lane & 7)) * 128;
    const uint32_t b_sel = ((lane >> 3) & 1);

    for (int kc = 0; kc < 16; kc++) {
        const int s = kc & 1;
        MBAR_WAIT(sb + 8 * s, (kc >> 1) & 1);

        const uint32_t st = st0 + s * STAGEB;
        const uint32_t tAH = st + 0 * TILEB;
        const uint32_t tAL = st + 1 * TILEB;
        const uint32_t tBH = st + 2 * TILEB;
        const uint32_t tBL = st + 3 * TILEB;

#pragma unroll
        for (int ks = 0; ks < 4; ks++) {
            const uint32_t ca = ((uint32_t)(ks * 2) + a_sel) ^ la7;
            const uint32_t cb = ((uint32_t)(ks * 2) + b_sel) ^ la7;
            uint32_t ah[2][4], al[2][4], bh[4][4], bl[4][4];
#pragma unroll
            for (int m2 = 0; m2 < 2; m2++) {
                LDSM4(ah[m2], tAH + a_row + m2 * 2048 + ca * 16);
                LDSM4(al[m2], tAL + a_row + m2 * 2048 + ca * 16);
            }
#pragma unroll
            for (int n2 = 0; n2 < 4; n2++) {
                LDSM4(bh[n2], tBH + b_row + n2 * 2048 + cb * 16);
                if (NTERMS == 3) LDSM4(bl[n2], tBL + b_row + n2 * 2048 + cb * 16);
            }
#pragma unroll
            for (int m2 = 0; m2 < 2; m2++)
#pragma unroll
                for (int n2 = 0; n2 < 4; n2++) {
                    MMA16816(acc[m2][n2 * 2 + 0], ah[m2], bh[n2][0], bh[n2][1]);
                    MMA16816(acc[m2][n2 * 2 + 1], ah[m2], bh[n2][2], bh[n2][3]);
                    MMA16816(acc[m2][n2 * 2 + 0], al[m2], bh[n2][0], bh[n2][1]);
                    MMA16816(acc[m2][n2 * 2 + 1], al[m2], bh[n2][2], bh[n2][3]);
                    if (NTERMS == 3) {
                        MMA16816(acc[m2][n2 * 2 + 0], ah[m2], bl[n2][0], bl[n2][1]);
                        MMA16816(acc[m2][n2 * 2 + 1], ah[m2], bl[n2][2], bl[n2][3]);
                    }
                }
        }
        __syncthreads();                 // all reads of stage s complete
        if (tid == 0 && kc + 2 < 16) load_stage(kc + 2, s);
    }

    const int rbase = mtb * 128 + wm * 32 + (lane >> 2);
    const int cbase = ntb * 128 + wn * 64 + (lane & 3) * 2;
#pragma unroll
    for (int m2 = 0; m2 < 2; m2++)
#pragma unroll
        for (int nt2 = 0; nt2 < 8; nt2++) {
            const int col = cbase + nt2 * 8;
            const float b0 = bias[col], b1 = bias[col + 1];
            float* p0 = C + (size_t)(rbase + m2 * 16) * EMB_ + col;
            float* p1 = p0 + 8 * EMB_;
            *(float2*)p0 = make_float2(acc[m2][nt2][0] + b0, acc[m2][nt2][1] + b1);
            *(float2*)p1 = make_float2(acc[m2][nt2][2] + b0, acc[m2][nt2][3] + b1);
        }
}

struct QKVArgs {
    const __half* ah[3];
    const __half* al[3];
    const __half* bh[3];
    const __half* bl[3];
    const float*  bias[3];
    float*        c[3];
};

__global__ __launch_bounds__(256, 1)
void gemm_qkv(QKVArgs a)     // z=0 Q (3t), z=1 K (3t), z=2 V (2t)
{
    extern __shared__ char smem[];
    const int z = blockIdx.z;
    if (z == 2)
        gemm_core<2>(a.ah[2], a.al[2], a.bh[2], nullptr, a.bias[2], a.c[2], smem);
    else
        gemm_core<3>(a.ah[z], a.al[z], a.bh[z], a.bl[z], a.bias[z], a.c[z], smem);
}

__global__ __launch_bounds__(256, 1)
void gemm_o(const __half* __restrict__ ah, const __half* __restrict__ al,
            const __half* __restrict__ bh, const float* __restrict__ bias,
            float* __restrict__ c)
{
    extern __shared__ char smem[];
    gemm_core<2>(ah, al, bh, nullptr, bias, c, smem);
}

// ---------------------------------------------------------------------------
// Per-token head-axis attention (fp32 in, tiled-swizzled fp16 hi/lo out).
// ---------------------------------------------------------------------------
__global__ __launch_bounds__(256)
void attn_head_mix(const float* __restrict__ q, const float* __restrict__ k,
                   const float* __restrict__ v,
                   __half* __restrict__ ohi, __half* __restrict__ olo)
{
    __shared__ float sq[NHEAD][68];
    __shared__ float skT[HDIM][17];
    __shared__ float sv[NHEAD][68];
    __shared__ float sa[NHEAD * NHEAD];

    const int t = blockIdx.x;
    const int tid = threadIdx.x;
    const size_t base = (size_t)t * EMB_;

    {
        const int e0 = tid * 4;
        const int h = e0 >> 6, d0 = e0 & 63;
        float4 q4 = *(const float4*)(q + base + e0);
        float4 k4 = *(const float4*)(k + base + e0);
        float4 v4 = *(const float4*)(v + base + e0);
        *(float4*)&sq[h][d0] = q4;
        *(float4*)&sv[h][d0] = v4;
        skT[d0 + 0][h] = k4.x;
        skT[d0 + 1][h] = k4.y;
        skT[d0 + 2][h] = k4.z;
        skT[d0 + 3][h] = k4.w;
    }
    __syncthreads();

    const int h = tid >> 4;
    const int g = tid & 15;
    float s = 0.0f;
#pragma unroll
    for (int d = 0; d < HDIM; d++) s = fmaf(sq[h][d], skT[d][g], s);
    s *= 0.125f;

    float m = s;
#pragma unroll
    for (int o = 8; o > 0; o >>= 1)
        m = fmaxf(m, __shfl_xor_sync(0xffffffffu, m, o, 16));
    const float e = __expf(s - m);
    float sum = e;
#pragma unroll
    for (int o = 8; o > 0; o >>= 1)
        sum += __shfl_xor_sync(0xffffffffu, sum, o, 16);
    sa[h * 16 + g] = e / sum;
    __syncthreads();

    const int ho = tid >> 4;
    const int d0 = (tid & 15) * 4;
    float o4[4] = {0.f, 0.f, 0.f, 0.f};
#pragma unroll
    for (int gg = 0; gg < NHEAD; gg++) {
        const float a = sa[ho * 16 + gg];
        float4 vv = *(const float4*)&sv[gg][d0];
        o4[0] = fmaf(a, vv.x, o4[0]);
        o4[1] = fmaf(a, vv.y, o4[1]);
        o4[2] = fmaf(a, vv.z, o4[2]);
        o4[3] = fmaf(a, vv.w, o4[3]);
    }

    ushort4 hv, lv;
    __half hb;
    hb = __float2half_rn(o4[0]); hv.x = __half_as_ushort(hb);
    lv.x = __half_as_ushort(__float2half_rn(o4[0] - __half2float(hb)));
    hb = __float2half_rn(o4[1]); hv.y = __half_as_ushort(hb);
    lv.y = __half_as_ushort(__float2half_rn(o4[1] - __half2float(hb)));
    hb = __float2half_rn(o4[2]); hv.z = __half_as_ushort(hb);
    lv.z = __half_as_ushort(__float2half_rn(o4[2] - __half2float(hb)));
    hb = __float2half_rn(o4[3]); hv.w = __half_as_ushort(hb);
    lv.w = __half_as_ushort(__float2half_rn(o4[3] - __half2float(hb)));

    // Tiled-swizzled store: row=t, cols ho*64 + d0 .. +3  (kc tile = ho).
    const int chunk = d0 >> 3;
    const size_t off = (((size_t)(t >> 7) * 16 + ho) << 14)
                     + (t & 127) * 128 + ((chunk ^ (t & 7)) << 4) + (d0 & 7) * 2;
    *(ushort4*)((char*)ohi + off) = hv;
    *(ushort4*)((char*)olo + off) = lv;
}

// ---------------------------------------------------------------------------
// Launch
// ---------------------------------------------------------------------------
extern "C" void kernel_launch(void* const* d_in, const int* in_sizes, int n_in,
                              void* d_out, int out_size)
{
    const float* values = (const float*)d_in[0];
    const float* keys   = (const float*)d_in[1];
    const float* query  = (const float*)d_in[2];
    const float* Wv = (const float*)d_in[3];
    const float* bv = (const float*)d_in[4];
    const float* Wk = (const float*)d_in[5];
    const float* bk = (const float*)d_in[6];
    const float* Wq = (const float*)d_in[7];
    const float* bq = (const float*)d_in[8];
    const float* Wo = (const float*)d_in[9];
    const float* bo = (const float*)d_in[10];
    float* out = (float*)d_out;

    static bool attr_set = false;
    if (!attr_set) {
        cudaFuncSetAttribute(gemm_qkv,
                             cudaFuncAttributeMaxDynamicSharedMemorySize, 1024 + 8 * TILEB);
        cudaFuncSetAttribute(gemm_o,
                             cudaFuncAttributeMaxDynamicSharedMemorySize, 1024 + 6 * TILEB);
        attr_set = true;
    }

    __half *vhi, *vlo, *khi, *klo, *qhi, *qlo;
    __half *wvhi, *wkhi, *wklo, *wqhi, *wqlo, *wohi;
    __half *ahi, *alo;
    float *gv, *gk, *gq;
    cudaGetSymbolAddress((void**)&vhi, g_vhi);   cudaGetSymbolAddress((void**)&vlo, g_vlo);
    cudaGetSymbolAddress((void**)&khi, g_khi);   cudaGetSymbolAddress((void**)&klo, g_klo);
    cudaGetSymbolAddress((void**)&qhi, g_qhi);   cudaGetSymbolAddress((void**)&qlo, g_qlo);
    cudaGetSymbolAddress((void**)&wvhi, g_wvhi);
    cudaGetSymbolAddress((void**)&wkhi, g_wkhi); cudaGetSymbolAddress((void**)&wklo, g_wklo);
    cudaGetSymbolAddress((void**)&wqhi, g_wqhi); cudaGetSymbolAddress((void**)&wqlo, g_wqlo);
    cudaGetSymbolAddress((void**)&wohi, g_wohi);
    cudaGetSymbolAddress((void**)&ahi, g_ahi);   cudaGetSymbolAddress((void**)&alo, g_alo);
    cudaGetSymbolAddress((void**)&gv, g_v);
    cudaGetSymbolAddress((void**)&gk, g_k);
    cudaGetSymbolAddress((void**)&gq, g_q);

    // Activation conversions (split), one launch.
    ConvArgs ca;
    ca.src[0] = values; ca.hi[0] = vhi; ca.lo[0] = vlo;
    ca.src[1] = keys;   ca.hi[1] = khi; ca.lo[1] = klo;
    ca.src[2] = query;  ca.hi[2] = qhi; ca.lo[2] = qlo;
    ca.src[3] = nullptr; ca.hi[3] = nullptr; ca.lo[3] = nullptr;
    conv_act<<<dim3(TOK * 128 / 256, 3), 256>>>(ca);

    // Weight conversions, one launch: Wq,Wk split; Wv,Wo round.
    ConvArgs cw;
    cw.src[0] = Wq; cw.hi[0] = wqhi; cw.lo[0] = wqlo;
    cw.src[1] = Wk; cw.hi[1] = wkhi; cw.lo[1] = wklo;
    cw.src[2] = Wv; cw.hi[2] = wvhi; cw.lo[2] = nullptr;
    cw.src[3] = Wo; cw.hi[3] = wohi; cw.lo[3] = nullptr;
    conv_w<<<dim3(EMB_ * 128 / 256, 4), 256>>>(cw);

    // Merged Q/K/V projections.
    QKVArgs a;
    a.ah[0] = qhi; a.al[0] = qlo; a.bh[0] = wqhi; a.bl[0] = wqlo; a.bias[0] = bq; a.c[0] = gq;
    a.ah[1] = khi; a.al[1] = klo; a.bh[1] = wkhi; a.bl[1] = wklo; a.bias[1] = bk; a.c[1] = gk;
    a.ah[2] = vhi; a.al[2] = vlo; a.bh[2] = wvhi; a.bl[2] = nullptr; a.bias[2] = bv; a.c[2] = gv;
    dim3 ggrid(EMB_ / 128, TOK / 128, 3);
    gemm_qkv<<<ggrid, 256, 1024 + 8 * TILEB>>>(a);

    attn_head_mix<<<TOK, 256>>>(gq, gk, gv, ahi, alo);

    dim3 ogrid(EMB_ / 128, TOK / 128);
    gemm_o<<<ogrid, 256, 1024 + 6 * TILEB>>>(ahi, alo, wohi, bo, out);
}

// round 6
// speedup vs baseline: 4.1326x; 1.1298x over previous
#include <cuda_runtime.h>
#include <cuda_fp16.h>
#include <cstdint>

// Problem constants (B=4, S=2048, EMB=1024, HEADS=16, HEAD_DIM=64)
#define TOK   8192
#define EMB_  1024
#define NHEAD 16
#define HDIM  64
#define TILEB 16384          // one 128-row x 128-byte (64 fp16) tile

// ---------------------------------------------------------------------------
// Scratch (device globals). Tiled-swizzled fp16:
// element (row, col) -> tile (row>>7, col>>6), inside: byte
//   (row&127)*128 + (((col&63)>>3) ^ (row&7))*16 + (col&7)*2
// ---------------------------------------------------------------------------
__device__ __half g_vhi[TOK * EMB_], g_vlo[TOK * EMB_];
__device__ __half g_khi[TOK * EMB_], g_klo[TOK * EMB_];
__device__ __half g_qhi[TOK * EMB_], g_qlo[TOK * EMB_];
__device__ __half g_wvhi[EMB_ * EMB_];
__device__ __half g_wkhi[EMB_ * EMB_];
__device__ __half g_wqhi[EMB_ * EMB_];
__device__ __half g_wohi[EMB_ * EMB_];
__device__ __half g_ahi[TOK * EMB_], g_alo[TOK * EMB_];
__device__ float g_v[TOK * EMB_], g_k[TOK * EMB_], g_q[TOK * EMB_];

// ---------------------------------------------------------------------------
// PTX helpers
// ---------------------------------------------------------------------------
__device__ __forceinline__ uint32_t smem_u32(const void* p) {
    uint32_t a;
    asm("{ .reg .u64 t; cvta.to.shared.u64 t, %1; cvt.u32.u64 %0, t; }"
        : "=r"(a) : "l"(p));
    return a;
}

#define MBAR_INIT(addr, cnt) \
    asm volatile("mbarrier.init.shared.b64 [%0], %1;" :: "r"(addr), "r"(cnt) : "memory")
#define MBAR_EXPECT_TX(addr, bytes) \
    asm volatile("mbarrier.arrive.expect_tx.shared.b64 _, [%0], %1;" \
                 :: "r"(addr), "r"(bytes) : "memory")
#define MBAR_WAIT(addr, parity) do { \
    uint32_t _m = (addr), _p = (parity), _done; \
    asm volatile("{ .reg .pred p; mbarrier.try_wait.parity.acquire.cta.shared::cta.b64 p, [%1], %2; selp.b32 %0, 1, 0, p; }" \
                 : "=r"(_done) : "r"(_m), "r"(_p) : "memory"); \
    if (!_done) { \
        asm volatile("{ .reg .pred P1; WL_%=: mbarrier.try_wait.parity.acquire.cta.shared::cta.b64 P1, [%0], %1, 0x989680; @P1 bra.uni WD_%=; bra.uni WL_%=; WD_%=: }" \
                     :: "r"(_m), "r"(_p) : "memory"); \
    } \
} while (0)

__device__ __forceinline__ void bulk_g2s(uint32_t dst, const void* src,
                                         uint32_t bytes, uint32_t mbar) {
    asm volatile(
        "cp.async.bulk.shared::cluster.global.mbarrier::complete_tx::bytes [%0], [%1], %2, [%3];"
        :: "r"(dst), "l"(src), "r"(bytes), "r"(mbar) : "memory");
}

#define LDSM4(R, addr) \
    asm volatile("ldmatrix.sync.aligned.m8n8.x4.shared.b16 {%0,%1,%2,%3}, [%4];" \
        : "=r"((R)[0]), "=r"((R)[1]), "=r"((R)[2]), "=r"((R)[3]) : "r"(addr))

#define MMA16816(D, A, B0, B1) \
    asm volatile("mma.sync.aligned.m16n8k16.row.col.f32.f16.f16.f32 " \
        "{%0,%1,%2,%3}, {%4,%5,%6,%7}, {%8,%9}, {%0,%1,%2,%3};" \
        : "+f"((D)[0]), "+f"((D)[1]), "+f"((D)[2]), "+f"((D)[3]) \
        : "r"((A)[0]), "r"((A)[1]), "r"((A)[2]), "r"((A)[3]), "r"(B0), "r"(B1))

// ---------------------------------------------------------------------------
// Conversions: fp32 row-major -> fp16 hi(/lo) in tiled-swizzled layout.
// ---------------------------------------------------------------------------
__device__ __forceinline__ void split_store(const float* __restrict__ src,
                                            __half* __restrict__ hi,
                                            __half* __restrict__ lo, int gid)
{
    const int row = gid >> 7;
    const int chunk = gid & 127;
    const int col0 = chunk << 3;
    const int kc = col0 >> 6;
    const int c16 = (col0 >> 3) & 7;

    const float4* sp = (const float4*)(src + (size_t)row * EMB_ + col0);
    float x[8];
    *(float4*)&x[0] = sp[0];
    *(float4*)&x[4] = sp[1];

    uint32_t hw[4], lw[4];
#pragma unroll
    for (int i = 0; i < 4; i++) {
        __half h0 = __float2half_rn(x[2 * i]);
        __half h1 = __float2half_rn(x[2 * i + 1]);
        hw[i] = (uint32_t)__half_as_ushort(h0) | ((uint32_t)__half_as_ushort(h1) << 16);
        if (lo) {
            __half l0 = __float2half_rn(x[2 * i]     - __half2float(h0));
            __half l1 = __float2half_rn(x[2 * i + 1] - __half2float(h1));
            lw[i] = (uint32_t)__half_as_ushort(l0) | ((uint32_t)__half_as_ushort(l1) << 16);
        }
    }
    const size_t off = (((size_t)(row >> 7) * 16 + kc) << 14)
                     + (row & 127) * 128 + ((c16 ^ (row & 7)) << 4);
    *(uint4*)((char*)hi + off) = make_uint4(hw[0], hw[1], hw[2], hw[3]);
    if (lo)
        *(uint4*)((char*)lo + off) = make_uint4(lw[0], lw[1], lw[2], lw[3]);
}

struct ConvArgs {
    const float* src[4];
    __half* hi[4];
    __half* lo[4];
};

__global__ __launch_bounds__(256)
void conv_act(ConvArgs a)   // grid (4096, 3): activations, split
{
    const int z = blockIdx.y;
    const int gid = blockIdx.x * 256 + threadIdx.x;
    split_store(a.src[z], a.hi[z], a.lo[z], gid);
}

__global__ __launch_bounds__(256)
void conv_w(ConvArgs a)     // grid (512, 4): all weights round-only
{
    const int z = blockIdx.y;
    const int gid = blockIdx.x * 256 + threadIdx.x;
    split_store(a.src[z], a.hi[z], nullptr, gid);
}

// ---------------------------------------------------------------------------
// 2-term split-fp16 HMMA GEMM: C ~= (Ah+Al)·Bh^T + bias
// Tile 128x128, K-chunk 64, 3-stage bulk-copy pipeline, 8 warps (4m x 2n).
// ---------------------------------------------------------------------------
#define STAGEB (3 * TILEB)              // Ah, Al, Bh
#define GSMEM  (1024 + 3 * STAGEB)      // 3 stages

__device__ __forceinline__
void gemm_core2(const __half* __restrict__ Ah, const __half* __restrict__ Al,
                const __half* __restrict__ Bh,
                const float* __restrict__ bias, float* __restrict__ C,
                char* smem)
{
    const uint32_t sb = smem_u32(smem);
    const int tid = threadIdx.x;
    const int wid = tid >> 5, lane = tid & 31;
    const int ntb = blockIdx.x, mtb = blockIdx.y;
    const int wm = wid >> 1, wn = wid & 1;

    if (tid == 0) {
        MBAR_INIT(sb + 0, 1);
        MBAR_INIT(sb + 8, 1);
        MBAR_INIT(sb + 16, 1);
    }
    __syncthreads();

    const uint32_t st0 = sb + 1024;
    const char* aH = (const char*)Ah + ((size_t)mtb * 16 << 14);
    const char* aL = (const char*)Al + ((size_t)mtb * 16 << 14);
    const char* bH = (const char*)Bh + ((size_t)ntb * 16 << 14);

    auto load_stage = [&](int kc, int s) {
        const uint32_t full = sb + 8 * s;
        MBAR_EXPECT_TX(full, STAGEB);
        const uint32_t d = st0 + s * STAGEB;
        const size_t o = (size_t)kc << 14;
        bulk_g2s(d + 0 * TILEB, aH + o, TILEB, full);
        bulk_g2s(d + 1 * TILEB, aL + o, TILEB, full);
        bulk_g2s(d + 2 * TILEB, bH + o, TILEB, full);
    };

    if (tid == 0) {
        load_stage(0, 0);
        load_stage(1, 1);
        load_stage(2, 2);
    }

    float acc[2][8][4];
#pragma unroll
    for (int a = 0; a < 2; a++)
#pragma unroll
        for (int b = 0; b < 8; b++)
#pragma unroll
            for (int c = 0; c < 4; c++) acc[a][b][c] = 0.0f;

    const uint32_t la7 = lane & 7;
    const uint32_t a_row = (uint32_t)(wm * 32 + (lane & 15)) * 128;
    const uint32_t a_sel = (lane >> 4);
    const uint32_t b_row = (uint32_t)(wn * 64 + ((lane >> 4) & 1) * 8 + (lane & 7)) * 128;
    const uint32_t b_sel = ((lane >> 3) & 1);

    int s = 0, par = 0;
    for (int kc = 0; kc < 16; kc++) {
        MBAR_WAIT(sb + 8 * s, par);

        const uint32_t st = st0 + s * STAGEB;
        const uint32_t tAH = st + 0 * TILEB;
        const uint32_t tAL = st + 1 * TILEB;
        const uint32_t tBH = st + 2 * TILEB;

#pragma unroll
        for (int ks = 0; ks < 4; ks++) {
            const uint32_t ca = ((uint32_t)(ks * 2) + a_sel) ^ la7;
            const uint32_t cb = ((uint32_t)(ks * 2) + b_sel) ^ la7;
            uint32_t ah[2][4], al[2][4], bh[4][4];
#pragma unroll
            for (int m2 = 0; m2 < 2; m2++) {
                LDSM4(ah[m2], tAH + a_row + m2 * 2048 + ca * 16);
                LDSM4(al[m2], tAL + a_row + m2 * 2048 + ca * 16);
            }
#pragma unroll
            for (int n2 = 0; n2 < 4; n2++)
                LDSM4(bh[n2], tBH + b_row + n2 * 2048 + cb * 16);
#pragma unroll
            for (int m2 = 0; m2 < 2; m2++)
#pragma unroll
                for (int n2 = 0; n2 < 4; n2++) {
                    MMA16816(acc[m2][n2 * 2 + 0], ah[m2], bh[n2][0], bh[n2][1]);
                    MMA16816(acc[m2][n2 * 2 + 1], ah[m2], bh[n2][2], bh[n2][3]);
                    MMA16816(acc[m2][n2 * 2 + 0], al[m2], bh[n2][0], bh[n2][1]);
                    MMA16816(acc[m2][n2 * 2 + 1], al[m2], bh[n2][2], bh[n2][3]);
                }
        }
        __syncthreads();
        if (tid == 0 && kc + 3 < 16) load_stage(kc + 3, s);
        if (++s == 3) { s = 0; par ^= 1; }
    }

    const int rbase = mtb * 128 + wm * 32 + (lane >> 2);
    const int cbase = ntb * 128 + wn * 64 + (lane & 3) * 2;
#pragma unroll
    for (int m2 = 0; m2 < 2; m2++)
#pragma unroll
        for (int nt2 = 0; nt2 < 8; nt2++) {
            const int col = cbase + nt2 * 8;
            const float b0 = bias[col], b1 = bias[col + 1];
            float* p0 = C + (size_t)(rbase + m2 * 16) * EMB_ + col;
            float* p1 = p0 + 8 * EMB_;
            *(float2*)p0 = make_float2(acc[m2][nt2][0] + b0, acc[m2][nt2][1] + b1);
            *(float2*)p1 = make_float2(acc[m2][nt2][2] + b0, acc[m2][nt2][3] + b1);
        }
}

struct QKVArgs {
    const __half* ah[3];
    const __half* al[3];
    const __half* bh[3];
    const float*  bias[3];
    float*        c[3];
};

__global__ __launch_bounds__(256, 1)
void gemm_qkv(QKVArgs a)
{
    extern __shared__ char smem[];
    const int z = blockIdx.z;
    gemm_core2(a.ah[z], a.al[z], a.bh[z], a.bias[z], a.c[z], smem);
}

__global__ __launch_bounds__(256, 1)
void gemm_o(const __half* __restrict__ ah, const __half* __restrict__ al,
            const __half* __restrict__ bh, const float* __restrict__ bias,
            float* __restrict__ c)
{
    extern __shared__ char smem[];
    gemm_core2(ah, al, bh, bias, c, smem);
}

// ---------------------------------------------------------------------------
// Per-token head-axis attention (fp32 in, tiled-swizzled fp16 hi/lo out).
// Score phase: 64 threads, 2x2 register blocking, float2 LDS.
// ---------------------------------------------------------------------------
__global__ __launch_bounds__(256)
void attn_head_mix(const float* __restrict__ q, const float* __restrict__ k,
                   const float* __restrict__ v,
                   __half* __restrict__ ohi, __half* __restrict__ olo)
{
    __shared__ float sq[NHEAD][68];
    __shared__ float skT[HDIM][18];
    __shared__ float sv[NHEAD][68];
    __shared__ float sa[NHEAD * NHEAD];

    const int t = blockIdx.x;
    const int tid = threadIdx.x;
    const size_t base = (size_t)t * EMB_;

    {
        const int e0 = tid * 4;
        const int h = e0 >> 6, d0 = e0 & 63;
        float4 q4 = *(const float4*)(q + base + e0);
        float4 k4 = *(const float4*)(k + base + e0);
        float4 v4 = *(const float4*)(v + base + e0);
        *(float4*)&sq[h][d0] = q4;
        *(float4*)&sv[h][d0] = v4;
        skT[d0 + 0][h] = k4.x;
        skT[d0 + 1][h] = k4.y;
        skT[d0 + 2][h] = k4.z;
        skT[d0 + 3][h] = k4.w;
    }
    __syncthreads();

    if (tid < 64) {
        const int h0 = (tid >> 3) << 1;     // 0,2,..,14
        const int g0 = (tid & 7) << 1;      // 0,2,..,14
        float s00 = 0.f, s01 = 0.f, s10 = 0.f, s11 = 0.f;
#pragma unroll
        for (int d = 0; d < HDIM; d += 2) {
            const float2 q0 = *(const float2*)&sq[h0][d];
            const float2 q1 = *(const float2*)&sq[h0 + 1][d];
            const float2 ka = *(const float2*)&skT[d][g0];
            const float2 kb = *(const float2*)&skT[d + 1][g0];
            s00 = fmaf(q0.x, ka.x, s00); s00 = fmaf(q0.y, kb.x, s00);
            s01 = fmaf(q0.x, ka.y, s01); s01 = fmaf(q0.y, kb.y, s01);
            s10 = fmaf(q1.x, ka.x, s10); s10 = fmaf(q1.y, kb.x, s10);
            s11 = fmaf(q1.x, ka.y, s11); s11 = fmaf(q1.y, kb.y, s11);
        }
        s00 *= 0.125f; s01 *= 0.125f; s10 *= 0.125f; s11 *= 0.125f;

        float m0 = fmaxf(s00, s01), m1 = fmaxf(s10, s11);
#pragma unroll
        for (int o = 4; o > 0; o >>= 1) {
            m0 = fmaxf(m0, __shfl_xor_sync(0xffffffffu, m0, o, 8));
            m1 = fmaxf(m1, __shfl_xor_sync(0xffffffffu, m1, o, 8));
        }
        const float e00 = __expf(s00 - m0), e01 = __expf(s01 - m0);
        const float e10 = __expf(s10 - m1), e11 = __expf(s11 - m1);
        float u0 = e00 + e01, u1 = e10 + e11;
#pragma unroll
        for (int o = 4; o > 0; o >>= 1) {
            u0 += __shfl_xor_sync(0xffffffffu, u0, o, 8);
            u1 += __shfl_xor_sync(0xffffffffu, u1, o, 8);
        }
        const float r0 = 1.0f / u0, r1 = 1.0f / u1;
        sa[h0 * 16 + g0]           = e00 * r0;
        sa[h0 * 16 + g0 + 1]       = e01 * r0;
        sa[(h0 + 1) * 16 + g0]     = e10 * r1;
        sa[(h0 + 1) * 16 + g0 + 1] = e11 * r1;
    }
    __syncthreads();

    const int ho = tid >> 4;
    const int d0 = (tid & 15) * 4;
    float o4[4] = {0.f, 0.f, 0.f, 0.f};
#pragma unroll
    for (int gg = 0; gg < NHEAD; gg++) {
        const float a = sa[ho * 16 + gg];
        float4 vv = *(const float4*)&sv[gg][d0];
        o4[0] = fmaf(a, vv.x, o4[0]);
        o4[1] = fmaf(a, vv.y, o4[1]);
        o4[2] = fmaf(a, vv.z, o4[2]);
        o4[3] = fmaf(a, vv.w, o4[3]);
    }

    ushort4 hv, lv;
    __half hb;
    hb = __float2half_rn(o4[0]); hv.x = __half_as_ushort(hb);
    lv.x = __half_as_ushort(__float2half_rn(o4[0] - __half2float(hb)));
    hb = __float2half_rn(o4[1]); hv.y = __half_as_ushort(hb);
    lv.y = __half_as_ushort(__float2half_rn(o4[1] - __half2float(hb)));
    hb = __float2half_rn(o4[2]); hv.z = __half_as_ushort(hb);
    lv.z = __half_as_ushort(__float2half_rn(o4[2] - __half2float(hb)));
    hb = __float2half_rn(o4[3]); hv.w = __half_as_ushort(hb);
    lv.w = __half_as_ushort(__float2half_rn(o4[3] - __half2float(hb)));

    const int chunk = d0 >> 3;
    const size_t off = (((size_t)(t >> 7) * 16 + ho) << 14)
                     + (t & 127) * 128 + ((chunk ^ (t & 7)) << 4) + (d0 & 7) * 2;
    *(ushort4*)((char*)ohi + off) = hv;
    *(ushort4*)((char*)olo + off) = lv;
}

// ---------------------------------------------------------------------------
// Launch
// ---------------------------------------------------------------------------
extern "C" void kernel_launch(void* const* d_in, const int* in_sizes, int n_in,
                              void* d_out, int out_size)
{
    const float* values = (const float*)d_in[0];
    const float* keys   = (const float*)d_in[1];
    const float* query  = (const float*)d_in[2];
    const float* Wv = (const float*)d_in[3];
    const float* bv = (const float*)d_in[4];
    const float* Wk = (const float*)d_in[5];
    const float* bk = (const float*)d_in[6];
    const float* Wq = (const float*)d_in[7];
    const float* bq = (const float*)d_in[8];
    const float* Wo = (const float*)d_in[9];
    const float* bo = (const float*)d_in[10];
    float* out = (float*)d_out;

    static bool attr_set = false;
    if (!attr_set) {
        cudaFuncSetAttribute(gemm_qkv,
                             cudaFuncAttributeMaxDynamicSharedMemorySize, GSMEM);
        cudaFuncSetAttribute(gemm_o,
                             cudaFuncAttributeMaxDynamicSharedMemorySize, GSMEM);
        attr_set = true;
    }

    __half *vhi, *vlo, *khi, *klo, *qhi, *qlo;
    __half *wvhi, *wkhi, *wqhi, *wohi;
    __half *ahi, *alo;
    float *gv, *gk, *gq;
    cudaGetSymbolAddress((void**)&vhi, g_vhi);   cudaGetSymbolAddress((void**)&vlo, g_vlo);
    cudaGetSymbolAddress((void**)&khi, g_khi);   cudaGetSymbolAddress((void**)&klo, g_klo);
    cudaGetSymbolAddress((void**)&qhi, g_qhi);   cudaGetSymbolAddress((void**)&qlo, g_qlo);
    cudaGetSymbolAddress((void**)&wvhi, g_wvhi);
    cudaGetSymbolAddress((void**)&wkhi, g_wkhi);
    cudaGetSymbolAddress((void**)&wqhi, g_wqhi);
    cudaGetSymbolAddress((void**)&wohi, g_wohi);
    cudaGetSymbolAddress((void**)&ahi, g_ahi);   cudaGetSymbolAddress((void**)&alo, g_alo);
    cudaGetSymbolAddress((void**)&gv, g_v);
    cudaGetSymbolAddress((void**)&gk, g_k);
    cudaGetSymbolAddress((void**)&gq, g_q);

    ConvArgs ca;
    ca.src[0] = values; ca.hi[0] = vhi; ca.lo[0] = vlo;
    ca.src[1] = keys;   ca.hi[1] = khi; ca.lo[1] = klo;
    ca.src[2] = query;  ca.hi[2] = qhi; ca.lo[2] = qlo;
    ca.src[3] = nullptr; ca.hi[3] = nullptr; ca.lo[3] = nullptr;
    conv_act<<<dim3(TOK * 128 / 256, 3), 256>>>(ca);

    ConvArgs cw;
    cw.src[0] = Wq; cw.hi[0] = wqhi; cw.lo[0] = nullptr;
    cw.src[1] = Wk; cw.hi[1] = wkhi; cw.lo[1] = nullptr;
    cw.src[2] = Wv; cw.hi[2] = wvhi; cw.lo[2] = nullptr;
    cw.src[3] = Wo; cw.hi[3] = wohi; cw.lo[3] = nullptr;
    conv_w<<<dim3(EMB_ * 128 / 256, 4), 256>>>(cw);

    QKVArgs a;
    a.ah[0] = qhi; a.al[0] = qlo; a.bh[0] = wqhi; a.bias[0] = bq; a.c[0] = gq;
    a.ah[1] = khi; a.al[1] = klo; a.bh[1] = wkhi; a.bias[1] = bk; a.c[1] = gk;
    a.ah[2] = vhi; a.al[2] = vlo; a.bh[2] = wvhi; a.bias[2] = bv; a.c[2] = gv;
    dim3 ggrid(EMB_ / 128, TOK / 128, 3);
    gemm_qkv<<<ggrid, 256, GSMEM>>>(a);

    attn_head_mix<<<TOK, 256>>>(gq, gk, gv, ahi, alo);

    dim3 ogrid(EMB_ / 128, TOK / 128);
    gemm_o<<<ogrid, 256, GSMEM>>>(ahi, alo, wohi, bo, out);
}